// round 5
// baseline (speedup 1.0000x reference)
#include <cuda_runtime.h>
#include <cuda_bf16.h>

#define HH 128
#define WWID 128
#define NBATCH 8
#define CIN 64
#define HW (HH*WWID)
#define STAGE_IC 4
#define NSTAGES (CIN / STAGE_IC)   // 16

// Scratch (allocation-free rule: __device__ globals)
__device__ float g_buf0[NBATCH * CIN * HW];
__device__ float g_buf1[NBATCH * CIN * HW];
__device__ float g_bcoef[NBATCH * 54 * HW];
__device__ float g_wT[6 * CIN * 9 * 64];   // [l][ic][k][oc], BN-scale folded
__device__ float g_shiftT[6 * 64];

typedef unsigned long long ull;

__device__ __forceinline__ ull ffma2(ull a, ull b, ull c) {
    ull d;
    asm("fma.rn.f32x2 %0, %1, %2, %3;" : "=l"(d) : "l"(a), "l"(b), "l"(c));
    return d;
}
__device__ __forceinline__ ull pack2(float a, float b) {
    ull r;
    asm("mov.b64 %0, {%1, %2};" : "=l"(r) : "f"(a), "f"(b));
    return r;
}
__device__ __forceinline__ void unpack2(ull v, float& lo, float& hi) {
    asm("mov.b64 {%0, %1}, %2;" : "=f"(lo), "=f"(hi) : "l"(v));
}
__device__ __forceinline__ float tanh_fast(float x) {
    float a = fminf(fmaxf(x, -9.f), 9.f);
    float e = __expf(2.f * a);
    return __fdividef(e - 1.f, e + 1.f);
}
__device__ __forceinline__ void cp4z(float* dst, const float* src, bool ok) {
    unsigned d = (unsigned)__cvta_generic_to_shared(dst);
    int sz = ok ? 4 : 0;
    asm volatile("cp.async.ca.shared.global [%0], [%1], 4, %2;" :: "r"(d), "l"(src), "r"(sz));
}
__device__ __forceinline__ void cp16(void* dst, const void* src) {
    unsigned d = (unsigned)__cvta_generic_to_shared(dst);
    asm volatile("cp.async.cg.shared.global [%0], [%1], 16;" :: "r"(d), "l"(src));
}

// ---------------------------------------------------------------------------
// Prep: fold BN scale into weights, transpose to [ic][k][oc]; compute shift.
// ---------------------------------------------------------------------------
__global__ void prep_weights(
    const float* __restrict__ w0, const float* __restrict__ b0,
    const float* __restrict__ g0, const float* __restrict__ be0,
    const float* __restrict__ m0, const float* __restrict__ v0,
    const float* __restrict__ wm, const float* __restrict__ bm,
    const float* __restrict__ gm, const float* __restrict__ bem,
    const float* __restrict__ mm, const float* __restrict__ vm,
    float* __restrict__ wT, float* __restrict__ shiftT)
{
    const int l = blockIdx.y;   // 0..5
    const int ic = blockIdx.x;  // 0..63
    const float *w, *bb, *g, *be, *m, *v;
    if (l == 0) { w = w0; bb = b0; g = g0; be = be0; m = m0; v = v0; }
    else {
        int i = l - 1;
        w = wm + (size_t)i * 64 * 64 * 9; bb = bm + i * 64; g = gm + i * 64;
        be = bem + i * 64; m = mm + i * 64; v = vm + i * 64;
    }
    for (int e = threadIdx.x; e < 576; e += blockDim.x) {
        int k = e >> 6, oc = e & 63;
        float sc = g[oc] * rsqrtf(v[oc] + 1e-5f);
        wT[(((size_t)l * 64 + ic) * 9 + k) * 64 + oc] =
            w[((size_t)oc * 64 + ic) * 9 + k] * sc;
    }
    if (ic == 0) {
        for (int oc = threadIdx.x; oc < 64; oc += blockDim.x) {
            float sc = g[oc] * rsqrtf(v[oc] + 1e-5f);
            shiftT[l * 64 + oc] = (bb[oc] - m[oc]) * sc + be[oc];
        }
    }
}

// ---------------------------------------------------------------------------
// conv3x3 + folded BN + tanh, 64->64, FFMA2 math, cp.async double-buffered.
// Block 256 = tx(16) * tyq(4) * grp(4); tile 16x16 pixels.
// Thread: 4 consecutive rows x 16 oc (8 f32x2 pairs).
// ---------------------------------------------------------------------------
__global__ __launch_bounds__(256, 2) void conv_bn_tanh64(
    const float* __restrict__ in, float* __restrict__ out,
    const float* __restrict__ wT, const float* __restrict__ shiftT)
{
    __shared__ __align__(16) float tile[2][STAGE_IC][324];
    __shared__ __align__(16) float wk[2][STAGE_IC * 576];
    __shared__ float s_shift[64];

    const int tid = threadIdx.x;
    const int tx  = tid & 15;
    const int tyq = (tid >> 4) & 3;
    const int grp = tid >> 6;
    const int bx = blockIdx.x << 4, by = blockIdx.y << 4, b = blockIdx.z;
    const int r0 = tyq * 4;

    if (tid < 64) s_shift[tid] = shiftT[tid];

    const float* inb = in + (size_t)b * CIN * HW;

    // ---- async stage copy: stage s (4 ics) into buffer buf ----
    auto issue_stage = [&](int s, int buf) {
        const int ic0 = s * STAGE_IC;
        #pragma unroll 1
        for (int i = tid; i < STAGE_IC * 324; i += 256) {
            int ic = i / 324, j = i - ic * 324;
            int r = j / 18, c = j - r * 18;
            int hh = by + r - 1, ww = bx + c - 1;
            bool ok = ((unsigned)hh < HH) && ((unsigned)ww < WWID);
            const float* src = ok ? (inb + (size_t)(ic0 + ic) * HW + hh * WWID + ww) : inb;
            cp4z(&tile[buf][ic][j], src, ok);
        }
        const float4* wsrc = (const float4*)(wT + (size_t)ic0 * 576);
        float4* wdst = (float4*)wk[buf];
        #pragma unroll 1
        for (int i = tid; i < STAGE_IC * 576 / 4; i += 256)
            cp16(&wdst[i], &wsrc[i]);
        asm volatile("cp.async.commit_group;" ::: "memory");
    };

    ull acc[4][8];
    #pragma unroll
    for (int p = 0; p < 4; p++)
        #pragma unroll
        for (int o = 0; o < 8; o++) acc[p][o] = 0ull;

    issue_stage(0, 0);
    issue_stage(1, 1);

    for (int s = 0; s < NSTAGES; s++) {
        asm volatile("cp.async.wait_group 1;" ::: "memory");
        __syncthreads();
        const int buf = s & 1;

        #pragma unroll
        for (int ic = 0; ic < STAGE_IC; ic++) {
            float va[6][3];
            #pragma unroll
            for (int rr = 0; rr < 6; rr++)
                #pragma unroll
                for (int dx = 0; dx < 3; dx++)
                    va[rr][dx] = tile[buf][ic][(r0 + rr) * 18 + tx + dx];

            const float* wbase = &wk[buf][ic * 576];
            #pragma unroll
            for (int k = 0; k < 9; k++) {
                const int dy = k / 3, dx = k - dy * 3;
                ull wp[8];
                const ull* wrow = (const ull*)(wbase + k * 64 + grp * 16);
                #pragma unroll
                for (int o = 0; o < 8; o++) wp[o] = wrow[o];
                #pragma unroll
                for (int p = 0; p < 4; p++) {
                    ull v2 = pack2(va[p + dy][dx], va[p + dy][dx]);
                    #pragma unroll
                    for (int o = 0; o < 8; o++)
                        acc[p][o] = ffma2(v2, wp[o], acc[p][o]);
                }
            }
        }

        __syncthreads();
        if (s + 2 < NSTAGES) issue_stage(s + 2, buf);
        else asm volatile("cp.async.commit_group;" ::: "memory");
    }

    float* outb = out + (size_t)b * CIN * HW;
    #pragma unroll
    for (int o = 0; o < 8; o++) {
        int oc0 = grp * 16 + 2 * o;
        float sh0 = s_shift[oc0], sh1 = s_shift[oc0 + 1];
        #pragma unroll
        for (int p = 0; p < 4; p++) {
            float lo, hi;
            unpack2(acc[p][o], lo, hi);
            int h = by + r0 + p;
            outb[(size_t)oc0 * HW + h * WWID + bx + tx]       = tanh_fast(lo + sh0);
            outb[(size_t)(oc0 + 1) * HW + h * WWID + bx + tx] = tanh_fast(hi + sh1);
        }
    }
}

// ---------------------------------------------------------------------------
// Last layer: conv3x3+BN+tanh 64 -> 36 fused with bcoef einsum.
// ---------------------------------------------------------------------------
__global__ __launch_bounds__(256) void conv_last_bcoef(
    const float* __restrict__ in, float* __restrict__ bco,
    const float* __restrict__ wgt, const float* __restrict__ bias,
    const float* __restrict__ gam, const float* __restrict__ bet,
    const float* __restrict__ mea, const float* __restrict__ var,
    const float* __restrict__ bases)
{
    __shared__ float tile[18 * 18];
    __shared__ float wsm[36 * 9];
    __shared__ float s_scale[36], s_shift[36];
    __shared__ float s_bases[54];
    __shared__ float hs[256 * 37];

    const int tid = threadIdx.x;
    const int tx  = tid & 15;
    const int tyq = (tid >> 4) & 3;
    const int grp = tid >> 6;
    const int bx = blockIdx.x << 4, by = blockIdx.y << 4, b = blockIdx.z;

    if (tid < 36) {
        float sc = gam[tid] * rsqrtf(var[tid] + 1e-5f);
        s_scale[tid] = sc;
        s_shift[tid] = (bias[tid] - mea[tid]) * sc + bet[tid];
    }
    if (tid < 54) s_bases[tid] = bases[tid];

    float acc[4][9];
    #pragma unroll
    for (int p = 0; p < 4; p++)
        #pragma unroll
        for (int o = 0; o < 9; o++) acc[p][o] = 0.f;

    const float* inb = in + (size_t)b * CIN * HW;

    for (int ic = 0; ic < CIN; ic++) {
        __syncthreads();
        for (int i = tid; i < 324; i += 256) {
            int r = i / 18, c = i - r * 18;
            int hh = by + r - 1, ww = bx + c - 1;
            float v = 0.f;
            if ((unsigned)hh < HH && (unsigned)ww < WWID)
                v = inb[ic * HW + hh * WWID + ww];
            tile[i] = v;
        }
        for (int i = tid; i < 324; i += 256) {
            int oc = i / 9, k = i - oc * 9;
            wsm[i] = wgt[oc * (CIN * 9) + ic * 9 + k];
        }
        __syncthreads();

        float vv[4][9];
        #pragma unroll
        for (int p = 0; p < 4; p++) {
            int rr0 = p * 4 + tyq;
            #pragma unroll
            for (int dy = 0; dy < 3; dy++)
                #pragma unroll
                for (int dx = 0; dx < 3; dx++)
                    vv[p][dy * 3 + dx] = tile[(rr0 + dy) * 18 + tx + dx];
        }
        const float* wg = wsm + grp * 9 * 9;
        #pragma unroll
        for (int o = 0; o < 9; o++) {
            float wr[9];
            #pragma unroll
            for (int k = 0; k < 9; k++) wr[k] = wg[o * 9 + k];
            #pragma unroll
            for (int p = 0; p < 4; p++)
                #pragma unroll
                for (int k = 0; k < 9; k++)
                    acc[p][o] = fmaf(vv[p][k], wr[k], acc[p][o]);
        }
    }

    #pragma unroll
    for (int o = 0; o < 9; o++) {
        int oc = grp * 9 + o;
        float sc = s_scale[oc], sh = s_shift[oc];
        #pragma unroll
        for (int p = 0; p < 4; p++) {
            int pix = (p * 4 + tyq) * 16 + tx;
            hs[pix * 37 + oc] = tanh_fast(acc[p][o] * sc + sh);
        }
    }
    __syncthreads();

    const int pix = tid;
    const int h = by + (pix >> 4), w = bx + (pix & 15);
    const float* hp = &hs[pix * 37];
    #pragma unroll
    for (int m = 0; m < 6; m++) {
        float hm[6];
        #pragma unroll
        for (int k = 0; k < 6; k++) hm[k] = hp[m * 6 + k];
        #pragma unroll
        for (int l = 0; l < 9; l++) {
            float s = 0.f;
            #pragma unroll
            for (int k = 0; k < 6; k++) s = fmaf(hm[k], s_bases[k * 9 + l], s);
            bco[((size_t)(b * 6 + m) * 9 + l) * HW + h * WWID + w] = s;
        }
    }
}

// ---------------------------------------------------------------------------
// Dynamic conv: out[b, c*6+m, h, w] = sum_l bcoef[b,m,l,h,w] * x_patch[l]
// ---------------------------------------------------------------------------
__global__ __launch_bounds__(256) void dynconv(
    const float* __restrict__ x, const float* __restrict__ bco,
    float* __restrict__ out)
{
    const int b = blockIdx.y;
    const int pix = blockIdx.x * 256 + threadIdx.x;
    const int h = pix >> 7, w = pix & 127;

    float bc[54];
    const float* bcb = bco + (size_t)b * 54 * HW + pix;
    #pragma unroll
    for (int i = 0; i < 54; i++) bc[i] = bcb[(size_t)i * HW];

    bool ok[9]; int off[9];
    #pragma unroll
    for (int dy = 0; dy < 3; dy++)
        #pragma unroll
        for (int dx = 0; dx < 3; dx++) {
            int k = dy * 3 + dx;
            int hh = h + dy - 1, ww = w + dx - 1;
            ok[k] = ((unsigned)hh < HH) && ((unsigned)ww < WWID);
            off[k] = hh * WWID + ww;
        }

    const float* xb = x + (size_t)b * CIN * HW;
    float* ob = out + (size_t)b * (CIN * 6) * HW + pix;

    for (int c = 0; c < CIN; c++) {
        const float* xc = xb + c * HW;
        float v[9];
        #pragma unroll
        for (int k = 0; k < 9; k++) v[k] = ok[k] ? __ldg(xc + off[k]) : 0.f;
        #pragma unroll
        for (int m = 0; m < 6; m++) {
            float s = 0.f;
            #pragma unroll
            for (int k = 0; k < 9; k++) s = fmaf(bc[m * 9 + k], v[k], s);
            ob[(size_t)(c * 6 + m) * HW] = s;
        }
    }
}

// ---------------------------------------------------------------------------
extern "C" void kernel_launch(void* const* d_in, const int* in_sizes, int n_in,
                              void* d_out, int out_size) {
    const float* x    = (const float*)d_in[0];
    const float* w0   = (const float*)d_in[1];
    const float* b0   = (const float*)d_in[2];
    const float* g0   = (const float*)d_in[3];
    const float* be0  = (const float*)d_in[4];
    const float* m0   = (const float*)d_in[5];
    const float* v0   = (const float*)d_in[6];
    const float* wm   = (const float*)d_in[7];
    const float* bm   = (const float*)d_in[8];
    const float* gm   = (const float*)d_in[9];
    const float* bem  = (const float*)d_in[10];
    const float* mm   = (const float*)d_in[11];
    const float* vm   = (const float*)d_in[12];
    const float* wl   = (const float*)d_in[13];
    const float* bl   = (const float*)d_in[14];
    const float* gl   = (const float*)d_in[15];
    const float* bel  = (const float*)d_in[16];
    const float* ml   = (const float*)d_in[17];
    const float* vl   = (const float*)d_in[18];
    const float* bases= (const float*)d_in[19];

    float *buf0, *buf1, *bco, *wT, *shiftT;
    cudaGetSymbolAddress((void**)&buf0, g_buf0);
    cudaGetSymbolAddress((void**)&buf1, g_buf1);
    cudaGetSymbolAddress((void**)&bco,  g_bcoef);
    cudaGetSymbolAddress((void**)&wT,   g_wT);
    cudaGetSymbolAddress((void**)&shiftT, g_shiftT);

    dim3 pgrd(64, 6);
    prep_weights<<<pgrd, 256>>>(w0, b0, g0, be0, m0, v0,
                                wm, bm, gm, bem, mm, vm, wT, shiftT);

    dim3 blk(256);
    dim3 grd(WWID / 16, HH / 16, NBATCH);

    conv_bn_tanh64<<<grd, blk>>>(x, buf0, wT, shiftT);

    float* bufs[2] = { buf0, buf1 };
    for (int i = 0; i < 5; i++) {
        const float* src = bufs[i & 1];
        float* dst = bufs[(i + 1) & 1];
        conv_bn_tanh64<<<grd, blk>>>(src, dst,
            wT + (size_t)(i + 1) * CIN * 9 * 64, shiftT + (i + 1) * 64);
    }
    conv_last_bcoef<<<grd, blk>>>(buf1, bco, wl, bl, gl, bel, ml, vl, bases);

    dim3 grd2(HW / 256, NBATCH);
    dynconv<<<grd2, blk>>>(x, bco, (float*)d_out);
}

// round 9
// speedup vs baseline: 1.6271x; 1.6271x over previous
#include <cuda_runtime.h>
#include <cuda_bf16.h>
#include <cstdint>

#define HH 128
#define WWID 128
#define NBATCH 8
#define CIN 64
#define HW (HH*WWID)

// ---------------- device scratch ----------------
__device__ __nv_bfloat16 g_p0h[NBATCH * HW * CIN];
__device__ __nv_bfloat16 g_p0l[NBATCH * HW * CIN];
__device__ __nv_bfloat16 g_p1h[NBATCH * HW * CIN];
__device__ __nv_bfloat16 g_p1l[NBATCH * HW * CIN];
__device__ float g_fbuf[NBATCH * CIN * HW];
__device__ float g_bcoef[NBATCH * 54 * HW];
__device__ __nv_bfloat16 g_wS[6 * 9 * 2 * 64 * 64];  // [l][tap][split][oc][ic]
__device__ float g_shiftT[6 * 64];

// smem layout (bytes):
//  A halo: 6 slots (dy 0..2 x split h/l) of 130 px * 144B = 18720B  -> 112320
//  B:     10 slots (tap-in-phase x split) of 64 oc * 144B = 9216B   -> 92160
//  acc:   reuses B region (128*66*4 = 33792)
//  shift: 256B
#define A_SLOT 18720u
#define B_OFF 112320u
#define B_SLOT 9216u
#define ACC_OFF B_OFF
#define SH_OFF 204480u
#define SMEM_BYTES 204800

__device__ __forceinline__ float tanh_fast(float x) {
    float a = fminf(fmaxf(x, -9.f), 9.f);
    float e = __expf(2.f * a);
    return __fdividef(e - 1.f, e + 1.f);
}
__device__ __forceinline__ void cp16(uint32_t dst, const void* src) {
    asm volatile("cp.async.cg.shared.global [%0], [%1], 16;" :: "r"(dst), "l"(src));
}
__device__ __forceinline__ uint32_t s2u(const void* p) {
    return (uint32_t)__cvta_generic_to_shared(p);
}
__device__ __forceinline__ void ldsm4(uint32_t* a, uint32_t addr) {
    asm volatile("ldmatrix.sync.aligned.m8n8.x4.shared.b16 {%0,%1,%2,%3}, [%4];"
                 : "=r"(a[0]), "=r"(a[1]), "=r"(a[2]), "=r"(a[3]) : "r"(addr));
}
__device__ __forceinline__ void ldsm2(uint32_t* b, uint32_t addr) {
    asm volatile("ldmatrix.sync.aligned.m8n8.x2.shared.b16 {%0,%1}, [%2];"
                 : "=r"(b[0]), "=r"(b[1]) : "r"(addr));
}
__device__ __forceinline__ void mma16816(float* c, const uint32_t* a, const uint32_t* b) {
    asm volatile("mma.sync.aligned.m16n8k16.row.col.f32.bf16.bf16.f32 "
                 "{%0,%1,%2,%3}, {%4,%5,%6,%7}, {%8,%9}, {%0,%1,%2,%3};"
                 : "+f"(c[0]), "+f"(c[1]), "+f"(c[2]), "+f"(c[3])
                 : "r"(a[0]), "r"(a[1]), "r"(a[2]), "r"(a[3]), "r"(b[0]), "r"(b[1]));
}

// ---------------------------------------------------------------------------
__global__ void prep_weights(
    const float* __restrict__ w0, const float* __restrict__ b0,
    const float* __restrict__ g0, const float* __restrict__ be0,
    const float* __restrict__ m0, const float* __restrict__ v0,
    const float* __restrict__ wm, const float* __restrict__ bm,
    const float* __restrict__ gm, const float* __restrict__ bem,
    const float* __restrict__ mm, const float* __restrict__ vm,
    __nv_bfloat16* __restrict__ wS, float* __restrict__ shiftT)
{
    const int tap = blockIdx.x, l = blockIdx.y;
    const float *w, *bb, *g, *be, *m, *v;
    if (l == 0) { w = w0; bb = b0; g = g0; be = be0; m = m0; v = v0; }
    else {
        int i = l - 1;
        w = wm + (size_t)i * 64 * 64 * 9; bb = bm + i * 64; g = gm + i * 64;
        be = bem + i * 64; m = mm + i * 64; v = vm + i * 64;
    }
    for (int e = threadIdx.x; e < 4096; e += blockDim.x) {
        int oc = e >> 6, ic = e & 63;
        float sc = g[oc] * rsqrtf(v[oc] + 1e-5f);
        float f = w[((size_t)oc * 64 + ic) * 9 + tap] * sc;
        __nv_bfloat16 hi = __float2bfloat16_rn(f);
        __nv_bfloat16 lo = __float2bfloat16_rn(f - __bfloat162float(hi));
        size_t base = ((size_t)l * 9 + tap) * 2 * 4096;
        wS[base + e] = hi;
        wS[base + 4096 + e] = lo;
    }
    if (tap == 0)
        for (int oc = threadIdx.x; oc < 64; oc += blockDim.x) {
            float sc = g[oc] * rsqrtf(v[oc] + 1e-5f);
            shiftT[l * 64 + oc] = (bb[oc] - m[oc]) * sc + be[oc];
        }
}

// ---------------------------------------------------------------------------
// x [b][c][h][w] fp32 -> channel-last bf16 hi/lo [b][h][w][c]
// ---------------------------------------------------------------------------
__global__ __launch_bounds__(128) void split_input(
    const float* __restrict__ x,
    __nv_bfloat16* __restrict__ XH, __nv_bfloat16* __restrict__ XL)
{
    const int w = threadIdx.x, r = blockIdx.x, b = blockIdx.y;
    unsigned hp[32], lp[32];
    #pragma unroll
    for (int j = 0; j < 32; j++) {
        float f0 = x[((size_t)(b * 64 + 2 * j) * 128 + r) * 128 + w];
        float f1 = x[((size_t)(b * 64 + 2 * j + 1) * 128 + r) * 128 + w];
        __nv_bfloat16 h0 = __float2bfloat16_rn(f0), h1 = __float2bfloat16_rn(f1);
        __nv_bfloat16 l0 = __float2bfloat16_rn(f0 - __bfloat162float(h0));
        __nv_bfloat16 l1 = __float2bfloat16_rn(f1 - __bfloat162float(h1));
        hp[j] = (unsigned)__bfloat16_as_ushort(h0) | ((unsigned)__bfloat16_as_ushort(h1) << 16);
        lp[j] = (unsigned)__bfloat16_as_ushort(l0) | ((unsigned)__bfloat16_as_ushort(l1) << 16);
    }
    size_t base = ((size_t)(b * 128 + r) * 128 + w) * 64;
    uint4* dh = (uint4*)(XH + base);
    uint4* dl = (uint4*)(XL + base);
    #pragma unroll
    for (int q = 0; q < 8; q++) {
        dh[q] = make_uint4(hp[4*q], hp[4*q+1], hp[4*q+2], hp[4*q+3]);
        dl[q] = make_uint4(lp[4*q], lp[4*q+1], lp[4*q+2], lp[4*q+3]);
    }
}

// ---------------------------------------------------------------------------
// Warp-MMA conv layer. CTA = (row r, batch b). 8 warps = 4 M-stripes(32px) x
// 2 N-halves(32oc). Warp: m32 x n32 via m16n8k16 bf16 HMMA.
// dx tap shift = +-144B in padded halo buffer (ldmatrix per-lane addresses).
// ---------------------------------------------------------------------------
__global__ __launch_bounds__(256) void conv_mma(
    const __nv_bfloat16* __restrict__ XH, const __nv_bfloat16* __restrict__ XL,
    __nv_bfloat16* __restrict__ YH, __nv_bfloat16* __restrict__ YL,
    float* __restrict__ f32out,
    const __nv_bfloat16* __restrict__ wSl, const float* __restrict__ shiftl)
{
    extern __shared__ __align__(16) char sm[];
    const uint32_t alu = s2u(sm);
    const int tid = threadIdx.x, lane = tid & 31, wid = tid >> 5;
    const int ms = wid >> 1, nh = wid & 1;
    const int r = blockIdx.x, b = blockIdx.y;

    // ldmatrix per-lane offsets (A: x4 over m16k16; B: x2 over n8k16)
    const uint32_t aoff = (uint32_t)(lane & 15) * 144u + (uint32_t)((lane >> 4) & 1) * 16u;
    const uint32_t boff = (uint32_t)(lane & 7) * 144u + (uint32_t)((lane >> 3) & 1) * 16u;

    if (tid < 64) ((float*)(sm + SH_OFF))[tid] = shiftl[tid];

    // zero halo edge pixels (buffer px 0 and 129) of all 6 A slots
    {
        uint4 z = make_uint4(0, 0, 0, 0);
        for (int i = tid; i < 96; i += 256) {
            int slot = i >> 4, jj = (i >> 3) & 1, c = i & 7;
            *(uint4*)(sm + slot * A_SLOT + (jj ? 129 : 0) * 144 + c * 16) = z;
        }
        if (r == 0 || r == 127) {   // whole off-image row buffers (both splits)
            int dy = r ? 2 : 0;
            char* base = sm + (dy * 2) * A_SLOT;
            for (int i = tid; i < 2340; i += 256)
                *(uint4*)(base + i * 16) = z;
        }
    }

    // ---- async copies: A halo rows + B taps 0..4 ----
    #pragma unroll
    for (int dy = 0; dy < 3; dy++) {
        int rimg = r + dy - 1;
        if ((unsigned)rimg >= (unsigned)HH) continue;
        size_t rowb = (size_t)(b * 128 + rimg) * 16384;   // bytes into plane
        #pragma unroll
        for (int s = 0; s < 2; s++) {
            const char* src = (const char*)(s ? XL : XH) + rowb;
            uint32_t dstb = alu + (uint32_t)(dy * 2 + s) * A_SLOT;
            for (int i = tid; i < 1024; i += 256) {
                int px = i >> 3, c = i & 7;
                cp16(dstb + (uint32_t)(px + 1) * 144u + (uint32_t)c * 16u,
                     src + px * 128 + c * 16);
            }
        }
    }
    for (int i = tid; i < 5120; i += 256) {
        int slot = i >> 9, j = i & 511;   // slot = tap*2+split, j = oc*8+chunk
        cp16(alu + B_OFF + (uint32_t)slot * B_SLOT + (uint32_t)(j >> 3) * 144u +
                 (uint32_t)(j & 7) * 16u,
             (const char*)wSl + (size_t)slot * 8192 + (size_t)j * 16);
    }
    asm volatile("cp.async.commit_group;" ::: "memory");
    asm volatile("cp.async.wait_group 0;" ::: "memory");
    __syncthreads();

    float cacc[2][4][4];
    #pragma unroll
    for (int mt = 0; mt < 2; mt++)
        #pragma unroll
        for (int nt = 0; nt < 4; nt++)
            #pragma unroll
            for (int j = 0; j < 4; j++) cacc[mt][nt][j] = 0.f;

    auto do_tap = [&](int tap, uint32_t bslot) {
        const int dy = tap / 3, dx = tap % 3;
        const uint32_t aH = alu + (uint32_t)(dy * 2) * A_SLOT + (uint32_t)dx * 144u;
        const uint32_t aL = aH + A_SLOT;
        const uint32_t bH = bslot, bL = bslot + B_SLOT;
        #pragma unroll
        for (int kc = 0; kc < 4; kc++) {
            const uint32_t kb = (uint32_t)kc * 32u;
            uint32_t ah[2][4], al[2][4];
            ldsm4(ah[0], aH + (uint32_t)(ms * 32) * 144u + kb + aoff);
            ldsm4(ah[1], aH + (uint32_t)(ms * 32 + 16) * 144u + kb + aoff);
            ldsm4(al[0], aL + (uint32_t)(ms * 32) * 144u + kb + aoff);
            ldsm4(al[1], aL + (uint32_t)(ms * 32 + 16) * 144u + kb + aoff);
            uint32_t bh[4][2], bl[4][2];
            #pragma unroll
            for (int nt = 0; nt < 4; nt++) {
                ldsm2(bh[nt], bH + (uint32_t)(nh * 32 + nt * 8) * 144u + kb + boff);
                ldsm2(bl[nt], bL + (uint32_t)(nh * 32 + nt * 8) * 144u + kb + boff);
            }
            #pragma unroll
            for (int mt = 0; mt < 2; mt++)
                #pragma unroll
                for (int nt = 0; nt < 4; nt++) {
                    mma16816(cacc[mt][nt], ah[mt], bh[nt]);   // Ah*Bh
                    mma16816(cacc[mt][nt], al[mt], bh[nt]);   // Al*Bh
                    mma16816(cacc[mt][nt], ah[mt], bl[nt]);   // Ah*Bl
                }
        }
    };

    for (int t = 0; t < 5; t++) do_tap(t, alu + B_OFF + (uint32_t)t * 2 * B_SLOT);
    __syncthreads();   // all reads of phase-1 B done

    // ---- B taps 5..8 into slots 0..7 ----
    for (int i = tid; i < 4096; i += 256) {
        int slot = i >> 9, j = i & 511;
        cp16(alu + B_OFF + (uint32_t)slot * B_SLOT + (uint32_t)(j >> 3) * 144u +
                 (uint32_t)(j & 7) * 16u,
             (const char*)wSl + (size_t)(slot + 10) * 8192 + (size_t)j * 16);
    }
    asm volatile("cp.async.commit_group;" ::: "memory");
    asm volatile("cp.async.wait_group 0;" ::: "memory");
    __syncthreads();

    for (int t = 5; t < 9; t++) do_tap(t, alu + B_OFF + (uint32_t)(t - 5) * 2 * B_SLOT);
    __syncthreads();   // B region now reusable as acc

    // ---- accumulators -> smem [128 px][66-stride fp32] ----
    float* acc = (float*)(sm + ACC_OFF);
    {
        const int rb = ms * 32 + (lane >> 2);
        const int cb = nh * 32 + (lane & 3) * 2;
        #pragma unroll
        for (int mt = 0; mt < 2; mt++)
            #pragma unroll
            for (int nt = 0; nt < 4; nt++) {
                int row = rb + mt * 16, col = cb + nt * 8;
                *(float2*)&acc[row * 66 + col] =
                    make_float2(cacc[mt][nt][0], cacc[mt][nt][1]);
                *(float2*)&acc[(row + 8) * 66 + col] =
                    make_float2(cacc[mt][nt][2], cacc[mt][nt][3]);
            }
    }
    __syncthreads();

    // ---- epilogue: tanh + split bf16 (+ optional fp32 NCHW) ----
    {
        const int px = tid >> 1, ocb = (tid & 1) * 32;
        const float* shp = (const float*)(sm + SH_OFF) + ocb;
        const float* ap = acc + px * 66 + ocb;
        unsigned hp[16], lp[16];
        #pragma unroll
        for (int j = 0; j < 16; j++) {
            float t0 = tanh_fast(ap[2 * j] + shp[2 * j]);
            float t1 = tanh_fast(ap[2 * j + 1] + shp[2 * j + 1]);
            __nv_bfloat16 h0 = __float2bfloat16_rn(t0), h1 = __float2bfloat16_rn(t1);
            __nv_bfloat16 l0 = __float2bfloat16_rn(t0 - __bfloat162float(h0));
            __nv_bfloat16 l1 = __float2bfloat16_rn(t1 - __bfloat162float(h1));
            hp[j] = (unsigned)__bfloat16_as_ushort(h0) | ((unsigned)__bfloat16_as_ushort(h1) << 16);
            lp[j] = (unsigned)__bfloat16_as_ushort(l0) | ((unsigned)__bfloat16_as_ushort(l1) << 16);
            if (f32out) {
                f32out[(size_t)(b * 64 + ocb + 2 * j) * HW + r * 128 + px] = t0;
                f32out[(size_t)(b * 64 + ocb + 2 * j + 1) * HW + r * 128 + px] = t1;
            }
        }
        size_t ybase = ((size_t)(b * 128 + r) * 128 + px) * 64 + ocb;
        uint4* dh = (uint4*)(YH + ybase);
        uint4* dl = (uint4*)(YL + ybase);
        #pragma unroll
        for (int q = 0; q < 4; q++) {
            dh[q] = make_uint4(hp[4*q], hp[4*q+1], hp[4*q+2], hp[4*q+3]);
            dl[q] = make_uint4(lp[4*q], lp[4*q+1], lp[4*q+2], lp[4*q+3]);
        }
    }
}

// ---------------------------------------------------------------------------
// Last layer: conv3x3+BN+tanh 64 -> 36 fused with bcoef einsum. (unchanged)
// ---------------------------------------------------------------------------
__global__ __launch_bounds__(256) void conv_last_bcoef(
    const float* __restrict__ in, float* __restrict__ bco,
    const float* __restrict__ wgt, const float* __restrict__ bias,
    const float* __restrict__ gam, const float* __restrict__ bet,
    const float* __restrict__ mea, const float* __restrict__ var,
    const float* __restrict__ bases)
{
    __shared__ float tile[18 * 18];
    __shared__ float wsm[36 * 9];
    __shared__ float s_scale[36], s_shift[36];
    __shared__ float s_bases[54];
    __shared__ float hs[256 * 37];

    const int tid = threadIdx.x;
    const int tx  = tid & 15;
    const int tyq = (tid >> 4) & 3;
    const int grp = tid >> 6;
    const int bx = blockIdx.x << 4, by = blockIdx.y << 4, b = blockIdx.z;

    if (tid < 36) {
        float sc = gam[tid] * rsqrtf(var[tid] + 1e-5f);
        s_scale[tid] = sc;
        s_shift[tid] = (bias[tid] - mea[tid]) * sc + bet[tid];
    }
    if (tid < 54) s_bases[tid] = bases[tid];

    float acc[4][9];
    #pragma unroll
    for (int p = 0; p < 4; p++)
        #pragma unroll
        for (int o = 0; o < 9; o++) acc[p][o] = 0.f;

    const float* inb = in + (size_t)b * CIN * HW;

    for (int ic = 0; ic < CIN; ic++) {
        __syncthreads();
        for (int i = tid; i < 324; i += 256) {
            int r = i / 18, c = i - r * 18;
            int hh = by + r - 1, ww = bx + c - 1;
            float v = 0.f;
            if ((unsigned)hh < HH && (unsigned)ww < WWID)
                v = inb[ic * HW + hh * WWID + ww];
            tile[i] = v;
        }
        for (int i = tid; i < 324; i += 256) {
            int oc = i / 9, k = i - oc * 9;
            wsm[i] = wgt[oc * (CIN * 9) + ic * 9 + k];
        }
        __syncthreads();

        float vv[4][9];
        #pragma unroll
        for (int p = 0; p < 4; p++) {
            int rr0 = p * 4 + tyq;
            #pragma unroll
            for (int dy = 0; dy < 3; dy++)
                #pragma unroll
                for (int dx = 0; dx < 3; dx++)
                    vv[p][dy * 3 + dx] = tile[(rr0 + dy) * 18 + tx + dx];
        }
        const float* wg = wsm + grp * 9 * 9;
        #pragma unroll
        for (int o = 0; o < 9; o++) {
            float wr[9];
            #pragma unroll
            for (int k = 0; k < 9; k++) wr[k] = wg[o * 9 + k];
            #pragma unroll
            for (int p = 0; p < 4; p++)
                #pragma unroll
                for (int k = 0; k < 9; k++)
                    acc[p][o] = fmaf(vv[p][k], wr[k], acc[p][o]);
        }
    }

    #pragma unroll
    for (int o = 0; o < 9; o++) {
        int oc = grp * 9 + o;
        float sc = s_scale[oc], sh = s_shift[oc];
        #pragma unroll
        for (int p = 0; p < 4; p++) {
            int pix = (p * 4 + tyq) * 16 + tx;
            hs[pix * 37 + oc] = tanh_fast(acc[p][o] * sc + sh);
        }
    }
    __syncthreads();

    const int pix = tid;
    const int h = by + (pix >> 4), w = bx + (pix & 15);
    const float* hp = &hs[pix * 37];
    #pragma unroll
    for (int m = 0; m < 6; m++) {
        float hm[6];
        #pragma unroll
        for (int k = 0; k < 6; k++) hm[k] = hp[m * 6 + k];
        #pragma unroll
        for (int l = 0; l < 9; l++) {
            float s = 0.f;
            #pragma unroll
            for (int k = 0; k < 6; k++) s = fmaf(hm[k], s_bases[k * 9 + l], s);
            bco[((size_t)(b * 6 + m) * 9 + l) * HW + h * WWID + w] = s;
        }
    }
}

// ---------------------------------------------------------------------------
__global__ __launch_bounds__(256) void dynconv(
    const float* __restrict__ x, const float* __restrict__ bco,
    float* __restrict__ out)
{
    const int b = blockIdx.y;
    const int pix = blockIdx.x * 256 + threadIdx.x;
    const int h = pix >> 7, w = pix & 127;

    float bc[54];
    const float* bcb = bco + (size_t)b * 54 * HW + pix;
    #pragma unroll
    for (int i = 0; i < 54; i++) bc[i] = bcb[(size_t)i * HW];

    bool ok[9]; int off[9];
    #pragma unroll
    for (int dy = 0; dy < 3; dy++)
        #pragma unroll
        for (int dx = 0; dx < 3; dx++) {
            int k = dy * 3 + dx;
            int hh = h + dy - 1, ww = w + dx - 1;
            ok[k] = ((unsigned)hh < HH) && ((unsigned)ww < WWID);
            off[k] = hh * WWID + ww;
        }

    const float* xb = x + (size_t)b * CIN * HW;
    float* ob = out + (size_t)b * (CIN * 6) * HW + pix;

    for (int c = 0; c < CIN; c++) {
        const float* xc = xb + c * HW;
        float v[9];
        #pragma unroll
        for (int k = 0; k < 9; k++) v[k] = ok[k] ? __ldg(xc + off[k]) : 0.f;
        #pragma unroll
        for (int m = 0; m < 6; m++) {
            float s = 0.f;
            #pragma unroll
            for (int k = 0; k < 9; k++) s = fmaf(bc[m * 9 + k], v[k], s);
            ob[(size_t)(c * 6 + m) * HW] = s;
        }
    }
}

// ---------------------------------------------------------------------------
extern "C" void kernel_launch(void* const* d_in, const int* in_sizes, int n_in,
                              void* d_out, int out_size) {
    const float* x    = (const float*)d_in[0];
    const float* w0   = (const float*)d_in[1];
    const float* b0   = (const float*)d_in[2];
    const float* g0   = (const float*)d_in[3];
    const float* be0  = (const float*)d_in[4];
    const float* m0   = (const float*)d_in[5];
    const float* v0   = (const float*)d_in[6];
    const float* wm   = (const float*)d_in[7];
    const float* bm   = (const float*)d_in[8];
    const float* gm   = (const float*)d_in[9];
    const float* bem  = (const float*)d_in[10];
    const float* mm   = (const float*)d_in[11];
    const float* vm   = (const float*)d_in[12];
    const float* wl   = (const float*)d_in[13];
    const float* bl   = (const float*)d_in[14];
    const float* gl   = (const float*)d_in[15];
    const float* bel  = (const float*)d_in[16];
    const float* ml   = (const float*)d_in[17];
    const float* vl   = (const float*)d_in[18];
    const float* bases= (const float*)d_in[19];

    __nv_bfloat16 *p0h, *p0l, *p1h, *p1l, *wS;
    float *fbuf, *bco, *shiftT;
    cudaGetSymbolAddress((void**)&p0h, g_p0h);
    cudaGetSymbolAddress((void**)&p0l, g_p0l);
    cudaGetSymbolAddress((void**)&p1h, g_p1h);
    cudaGetSymbolAddress((void**)&p1l, g_p1l);
    cudaGetSymbolAddress((void**)&fbuf, g_fbuf);
    cudaGetSymbolAddress((void**)&bco,  g_bcoef);
    cudaGetSymbolAddress((void**)&wS,   g_wS);
    cudaGetSymbolAddress((void**)&shiftT, g_shiftT);

    cudaFuncSetAttribute(conv_mma, cudaFuncAttributeMaxDynamicSharedMemorySize, SMEM_BYTES);

    dim3 pgrd(9, 6);
    prep_weights<<<pgrd, 256>>>(w0, b0, g0, be0, m0, v0,
                                wm, bm, gm, bem, mm, vm, wS, shiftT);

    dim3 sgrd(128, NBATCH);
    split_input<<<sgrd, 128>>>(x, p0h, p0l);

    __nv_bfloat16* hbuf[2] = { p0h, p1h };
    __nv_bfloat16* lbuf[2] = { p0l, p1l };
    for (int l = 0; l < 6; l++) {
        conv_mma<<<sgrd, 256, SMEM_BYTES>>>(
            hbuf[l & 1], lbuf[l & 1], hbuf[(l + 1) & 1], lbuf[(l + 1) & 1],
            (l == 5) ? fbuf : (float*)nullptr,
            wS + (size_t)l * 9 * 2 * 4096, shiftT + l * 64);
    }

    dim3 grd(WWID / 16, HH / 16, NBATCH);
    conv_last_bcoef<<<grd, 256>>>(fbuf, bco, wl, bl, gl, bel, ml, vl, bases);

    dim3 grd2(HW / 256, NBATCH);
    dynconv<<<grd2, 256>>>(x, bco, (float*)d_out);
}

// round 10
// speedup vs baseline: 1.7998x; 1.1061x over previous
#include <cuda_runtime.h>
#include <cuda_bf16.h>
#include <cstdint>

#define HH 128
#define WWID 128
#define NBATCH 8
#define CIN 64
#define HW (HH*WWID)

// ---------------- device scratch ----------------
__device__ __nv_bfloat16 g_p0h[NBATCH * HW * CIN];
__device__ __nv_bfloat16 g_p0l[NBATCH * HW * CIN];
__device__ __nv_bfloat16 g_p1h[NBATCH * HW * CIN];
__device__ __nv_bfloat16 g_p1l[NBATCH * HW * CIN];
__device__ float g_bcoef[NBATCH * 54 * HW];
__device__ uint32_t g_wF[7 * 36864];     // [l][tap][kc][nh][lane][16] fragment regs
__device__ float g_shiftT[7 * 64];

// smem layout (bytes): A halo 6 slots (dy x split) of 130px*144B; shift; bases.
// acc (128*66*4=33792B) and hs (128*40*4) reuse the A region after mainloop.
#define A_SLOT 18720u
#define SH_OFF 112320u
#define BAS_OFF 112576u
#define HS_OFF 34816u
#define SMEM_BYTES 112896

__device__ __forceinline__ float tanh_fast(float x) {
    float a = fminf(fmaxf(x, -9.f), 9.f);
    float e = __expf(2.f * a);
    return __fdividef(e - 1.f, e + 1.f);
}
__device__ __forceinline__ void cp16(uint32_t dst, const void* src) {
    asm volatile("cp.async.cg.shared.global [%0], [%1], 16;" :: "r"(dst), "l"(src));
}
__device__ __forceinline__ uint32_t s2u(const void* p) {
    return (uint32_t)__cvta_generic_to_shared(p);
}
__device__ __forceinline__ void ldsm4(uint32_t* a, uint32_t addr) {
    asm volatile("ldmatrix.sync.aligned.m8n8.x4.shared.b16 {%0,%1,%2,%3}, [%4];"
                 : "=r"(a[0]), "=r"(a[1]), "=r"(a[2]), "=r"(a[3]) : "r"(addr));
}
__device__ __forceinline__ void mma16816(float* c, const uint32_t* a, const uint32_t* b) {
    asm volatile("mma.sync.aligned.m16n8k16.row.col.f32.bf16.bf16.f32 "
                 "{%0,%1,%2,%3}, {%4,%5,%6,%7}, {%8,%9}, {%0,%1,%2,%3};"
                 : "+f"(c[0]), "+f"(c[1]), "+f"(c[2]), "+f"(c[3])
                 : "r"(a[0]), "r"(a[1]), "r"(a[2]), "r"(a[3]), "r"(b[0]), "r"(b[1]));
}

// ---------------------------------------------------------------------------
// Prep: BN-fold weights, split bf16 hi/lo, write exact per-lane MMA fragments.
// Fragment reg value at (kc, nh, lane, r): r = split*8 + nt*2 + j,
//   n = nh*32 + nt*8 + lane/4,  k = kc*16 + (lane%4)*2 + j*8,
//   pair = split(w[n][k]), split(w[n][k+1])   (bf16x2)
// Layers 0..5: 64 oc. Layer 6 (last): 36 oc padded with zeros.
// ---------------------------------------------------------------------------
__global__ void prep_weights(
    const float* __restrict__ w0, const float* __restrict__ b0,
    const float* __restrict__ g0, const float* __restrict__ be0,
    const float* __restrict__ m0, const float* __restrict__ v0,
    const float* __restrict__ wm, const float* __restrict__ bm,
    const float* __restrict__ gm, const float* __restrict__ bem,
    const float* __restrict__ mm, const float* __restrict__ vm,
    const float* __restrict__ wl, const float* __restrict__ bl,
    const float* __restrict__ gl, const float* __restrict__ bel,
    const float* __restrict__ ml, const float* __restrict__ vl,
    uint32_t* __restrict__ wF, float* __restrict__ shiftT)
{
    const int tap = blockIdx.x, l = blockIdx.y;
    const float *w, *bb, *g, *be, *m, *v;
    int OC = 64;
    if (l == 0)      { w = w0; bb = b0; g = g0; be = be0; m = m0; v = v0; }
    else if (l <= 5) {
        int i = l - 1;
        w = wm + (size_t)i * 64 * 64 * 9; bb = bm + i * 64; g = gm + i * 64;
        be = bem + i * 64; m = mm + i * 64; v = vm + i * 64;
    } else { w = wl; bb = bl; g = gl; be = bel; m = ml; v = vl; OC = 36; }

    uint32_t* out = wF + (size_t)(l * 9 + tap) * 4096;
    for (int e = threadIdx.x; e < 4096; e += blockDim.x) {
        int kc = e >> 10, nh = (e >> 9) & 1, lane = (e >> 4) & 31, r = e & 15;
        int split = r >> 3, rr = r & 7, nt = rr >> 1, j = rr & 1;
        int n = nh * 32 + nt * 8 + (lane >> 2);
        int k = kc * 16 + (lane & 3) * 2 + j * 8;
        float f0 = 0.f, f1 = 0.f;
        if (n < OC) {
            float sc = g[n] * rsqrtf(v[n] + 1e-5f);
            f0 = w[((size_t)n * 64 + k) * 9 + tap] * sc;
            f1 = w[((size_t)n * 64 + k + 1) * 9 + tap] * sc;
        }
        __nv_bfloat16 h0 = __float2bfloat16_rn(f0), h1 = __float2bfloat16_rn(f1);
        unsigned v0, v1;
        if (split == 0) { v0 = __bfloat16_as_ushort(h0); v1 = __bfloat16_as_ushort(h1); }
        else {
            v0 = __bfloat16_as_ushort(__float2bfloat16_rn(f0 - __bfloat162float(h0)));
            v1 = __bfloat16_as_ushort(__float2bfloat16_rn(f1 - __bfloat162float(h1)));
        }
        out[e] = v0 | (v1 << 16);
    }
    if (tap == 0)
        for (int oc = threadIdx.x; oc < 64; oc += blockDim.x) {
            float s = 0.f;
            if (oc < OC) {
                float sc = g[oc] * rsqrtf(v[oc] + 1e-5f);
                s = (bb[oc] - m[oc]) * sc + be[oc];
            }
            shiftT[l * 64 + oc] = s;
        }
}

// ---------------------------------------------------------------------------
// x [b][c][h][w] fp32 -> channel-last bf16 hi/lo [b][h][w][c]
// ---------------------------------------------------------------------------
__global__ __launch_bounds__(128) void split_input(
    const float* __restrict__ x,
    __nv_bfloat16* __restrict__ XH, __nv_bfloat16* __restrict__ XL)
{
    const int w = threadIdx.x, r = blockIdx.x, b = blockIdx.y;
    unsigned hp[32], lp[32];
    #pragma unroll
    for (int j = 0; j < 32; j++) {
        float f0 = x[((size_t)(b * 64 + 2 * j) * 128 + r) * 128 + w];
        float f1 = x[((size_t)(b * 64 + 2 * j + 1) * 128 + r) * 128 + w];
        __nv_bfloat16 h0 = __float2bfloat16_rn(f0), h1 = __float2bfloat16_rn(f1);
        __nv_bfloat16 l0 = __float2bfloat16_rn(f0 - __bfloat162float(h0));
        __nv_bfloat16 l1 = __float2bfloat16_rn(f1 - __bfloat162float(h1));
        hp[j] = (unsigned)__bfloat16_as_ushort(h0) | ((unsigned)__bfloat16_as_ushort(h1) << 16);
        lp[j] = (unsigned)__bfloat16_as_ushort(l0) | ((unsigned)__bfloat16_as_ushort(l1) << 16);
    }
    size_t base = ((size_t)(b * 128 + r) * 128 + w) * 64;
    uint4* dh = (uint4*)(XH + base);
    uint4* dl = (uint4*)(XL + base);
    #pragma unroll
    for (int q = 0; q < 8; q++) {
        dh[q] = make_uint4(hp[4*q], hp[4*q+1], hp[4*q+2], hp[4*q+3]);
        dl[q] = make_uint4(lp[4*q], lp[4*q+1], lp[4*q+2], lp[4*q+3]);
    }
}

// ---------------------------------------------------------------------------
// Warp-MMA conv layer, B fragments via LDG (no B smem). CTA = (row, batch).
// 8 warps = 4 M-stripes(32px) x 2 N-halves(32oc). A halo in smem only.
// LAST=0: BN+tanh -> bf16 hi/lo planes.  LAST=1 (64->36): + bcoef einsum.
// ---------------------------------------------------------------------------
template<int LAST>
__global__ __launch_bounds__(256) void conv_mma_t(
    const __nv_bfloat16* __restrict__ XH, const __nv_bfloat16* __restrict__ XL,
    __nv_bfloat16* __restrict__ YH, __nv_bfloat16* __restrict__ YL,
    const uint32_t* __restrict__ wFl, const float* __restrict__ shiftl,
    const float* __restrict__ bases, float* __restrict__ bco)
{
    extern __shared__ __align__(16) char sm[];
    const uint32_t alu = s2u(sm);
    const int tid = threadIdx.x, lane = tid & 31, wid = tid >> 5;
    const int ms = wid >> 1, nh = wid & 1;
    const int r = blockIdx.x, b = blockIdx.y;

    const uint32_t aoff = (uint32_t)(lane & 15) * 144u + (uint32_t)((lane >> 4) & 1) * 16u;

    if (tid < 64) ((float*)(sm + SH_OFF))[tid] = shiftl[tid];
    if (LAST && tid < 54) ((float*)(sm + BAS_OFF))[tid] = bases[tid];

    // zero halo edge pixels (px 0, 129) of all 6 A slots; off-image rows
    {
        uint4 z = make_uint4(0, 0, 0, 0);
        for (int i = tid; i < 96; i += 256) {
            int slot = i >> 4, jj = (i >> 3) & 1, c = i & 7;
            *(uint4*)(sm + slot * A_SLOT + (jj ? 129 : 0) * 144 + c * 16) = z;
        }
        if (r == 0 || r == 127) {
            int dy = r ? 2 : 0;
            char* base = sm + (dy * 2) * A_SLOT;
            for (int i = tid; i < 2340; i += 256)
                *(uint4*)(base + i * 16) = z;
        }
    }

    // ---- async copies: A halo rows (hi/lo) ----
    #pragma unroll
    for (int dy = 0; dy < 3; dy++) {
        int rimg = r + dy - 1;
        if ((unsigned)rimg >= (unsigned)HH) continue;
        size_t rowb = (size_t)(b * 128 + rimg) * 16384;
        #pragma unroll
        for (int s = 0; s < 2; s++) {
            const char* src = (const char*)(s ? XL : XH) + rowb;
            uint32_t dstb = alu + (uint32_t)(dy * 2 + s) * A_SLOT;
            for (int i = tid; i < 1024; i += 256) {
                int px = i >> 3, c = i & 7;
                cp16(dstb + (uint32_t)(px + 1) * 144u + (uint32_t)c * 16u,
                     src + px * 128 + c * 16);
            }
        }
    }
    asm volatile("cp.async.commit_group;" ::: "memory");
    asm volatile("cp.async.wait_group 0;" ::: "memory");
    __syncthreads();

    float cacc[2][4][4];
    #pragma unroll
    for (int mt = 0; mt < 2; mt++)
        #pragma unroll
        for (int nt = 0; nt < 4; nt++)
            #pragma unroll
            for (int j = 0; j < 4; j++) cacc[mt][nt][j] = 0.f;

    // ---- mainloop: 9 taps, B fragments straight from global ----
    #pragma unroll 1
    for (int tap = 0; tap < 9; tap++) {
        const int dy = tap / 3, dx = tap % 3;
        const uint32_t aH = alu + (uint32_t)(dy * 2) * A_SLOT + (uint32_t)dx * 144u;
        const uint32_t aL = aH + A_SLOT;
        #pragma unroll
        for (int kc = 0; kc < 4; kc++) {
            const uint4* f = (const uint4*)(wFl +
                ((((size_t)tap * 4 + kc) * 2 + nh) * 32 + lane) * 16);
            uint4 q0 = f[0], q1 = f[1], q2 = f[2], q3 = f[3];

            const uint32_t kb = (uint32_t)kc * 32u;
            uint32_t ah[2][4], al[2][4];
            ldsm4(ah[0], aH + (uint32_t)(ms * 32) * 144u + kb + aoff);
            ldsm4(ah[1], aH + (uint32_t)(ms * 32 + 16) * 144u + kb + aoff);
            ldsm4(al[0], aL + (uint32_t)(ms * 32) * 144u + kb + aoff);
            ldsm4(al[1], aL + (uint32_t)(ms * 32 + 16) * 144u + kb + aoff);

            uint32_t bh[4][2], bl[4][2];
            bh[0][0] = q0.x; bh[0][1] = q0.y; bh[1][0] = q0.z; bh[1][1] = q0.w;
            bh[2][0] = q1.x; bh[2][1] = q1.y; bh[3][0] = q1.z; bh[3][1] = q1.w;
            bl[0][0] = q2.x; bl[0][1] = q2.y; bl[1][0] = q2.z; bl[1][1] = q2.w;
            bl[2][0] = q3.x; bl[2][1] = q3.y; bl[3][0] = q3.z; bl[3][1] = q3.w;

            #pragma unroll
            for (int mt = 0; mt < 2; mt++)
                #pragma unroll
                for (int nt = 0; nt < 4; nt++) {
                    mma16816(cacc[mt][nt], ah[mt], bh[nt]);   // Ah*Bh
                    mma16816(cacc[mt][nt], al[mt], bh[nt]);   // Al*Bh
                    mma16816(cacc[mt][nt], ah[mt], bl[nt]);   // Ah*Bl
                }
        }
    }
    __syncthreads();   // A region now reusable as acc

    // ---- accumulators -> smem [128 px][66-stride fp32] (reuses A region) ----
    float* acc = (float*)sm;
    {
        const int rb = ms * 32 + (lane >> 2);
        const int cb = nh * 32 + (lane & 3) * 2;
        #pragma unroll
        for (int mt = 0; mt < 2; mt++)
            #pragma unroll
            for (int nt = 0; nt < 4; nt++) {
                int row = rb + mt * 16, col = cb + nt * 8;
                *(float2*)&acc[row * 66 + col] =
                    make_float2(cacc[mt][nt][0], cacc[mt][nt][1]);
                *(float2*)&acc[(row + 8) * 66 + col] =
                    make_float2(cacc[mt][nt][2], cacc[mt][nt][3]);
            }
    }
    __syncthreads();

    if (!LAST) {
        // ---- epilogue: tanh + split bf16 planes ----
        const int px = tid >> 1, ocb = (tid & 1) * 32;
        const float* shp = (const float*)(sm + SH_OFF) + ocb;
        const float* ap = acc + px * 66 + ocb;
        unsigned hp[16], lp[16];
        #pragma unroll
        for (int j = 0; j < 16; j++) {
            float t0 = tanh_fast(ap[2 * j] + shp[2 * j]);
            float t1 = tanh_fast(ap[2 * j + 1] + shp[2 * j + 1]);
            __nv_bfloat16 h0 = __float2bfloat16_rn(t0), h1 = __float2bfloat16_rn(t1);
            __nv_bfloat16 l0 = __float2bfloat16_rn(t0 - __bfloat162float(h0));
            __nv_bfloat16 l1 = __float2bfloat16_rn(t1 - __bfloat162float(h1));
            hp[j] = (unsigned)__bfloat16_as_ushort(h0) | ((unsigned)__bfloat16_as_ushort(h1) << 16);
            lp[j] = (unsigned)__bfloat16_as_ushort(l0) | ((unsigned)__bfloat16_as_ushort(l1) << 16);
        }
        size_t ybase = ((size_t)(b * 128 + r) * 128 + px) * 64 + ocb;
        uint4* dh = (uint4*)(YH + ybase);
        uint4* dl = (uint4*)(YL + ybase);
        #pragma unroll
        for (int q = 0; q < 4; q++) {
            dh[q] = make_uint4(hp[4*q], hp[4*q+1], hp[4*q+2], hp[4*q+3]);
            dl[q] = make_uint4(lp[4*q], lp[4*q+1], lp[4*q+2], lp[4*q+3]);
        }
    } else {
        // ---- epilogue: tanh (36 oc) -> hs, then bcoef einsum ----
        float* hsP = (float*)(sm + HS_OFF);
        const float* shp = (const float*)(sm + SH_OFF);
        {
            const int px = tid >> 1, half = tid & 1;
            #pragma unroll
            for (int j = 0; j < 18; j++) {
                int oc = half * 18 + j;
                hsP[px * 40 + oc] = tanh_fast(acc[px * 66 + oc] + shp[oc]);
            }
        }
        __syncthreads();
        {
            const int px = tid >> 1, half = tid & 1;
            const float* basS = (const float*)(sm + BAS_OFF);
            const float* hp = hsP + px * 40;
            #pragma unroll
            for (int mm = 0; mm < 3; mm++) {
                int m = half * 3 + mm;
                float hm[6];
                #pragma unroll
                for (int k = 0; k < 6; k++) hm[k] = hp[m * 6 + k];
                #pragma unroll
                for (int l = 0; l < 9; l++) {
                    float s = 0.f;
                    #pragma unroll
                    for (int k = 0; k < 6; k++) s = fmaf(hm[k], basS[k * 9 + l], s);
                    bco[((size_t)(b * 6 + m) * 9 + l) * HW + r * 128 + px] = s;
                }
            }
        }
    }
}

// ---------------------------------------------------------------------------
__global__ __launch_bounds__(256) void dynconv(
    const float* __restrict__ x, const float* __restrict__ bco,
    float* __restrict__ out)
{
    const int b = blockIdx.y;
    const int pix = blockIdx.x * 256 + threadIdx.x;
    const int h = pix >> 7, w = pix & 127;

    float bc[54];
    const float* bcb = bco + (size_t)b * 54 * HW + pix;
    #pragma unroll
    for (int i = 0; i < 54; i++) bc[i] = bcb[(size_t)i * HW];

    bool ok[9]; int off[9];
    #pragma unroll
    for (int dy = 0; dy < 3; dy++)
        #pragma unroll
        for (int dx = 0; dx < 3; dx++) {
            int k = dy * 3 + dx;
            int hh = h + dy - 1, ww = w + dx - 1;
            ok[k] = ((unsigned)hh < HH) && ((unsigned)ww < WWID);
            off[k] = hh * WWID + ww;
        }

    const float* xb = x + (size_t)b * CIN * HW;
    float* ob = out + (size_t)b * (CIN * 6) * HW + pix;

    for (int c = 0; c < CIN; c++) {
        const float* xc = xb + c * HW;
        float v[9];
        #pragma unroll
        for (int k = 0; k < 9; k++) v[k] = ok[k] ? __ldg(xc + off[k]) : 0.f;
        #pragma unroll
        for (int m = 0; m < 6; m++) {
            float s = 0.f;
            #pragma unroll
            for (int k = 0; k < 9; k++) s = fmaf(bc[m * 9 + k], v[k], s);
            ob[(size_t)(c * 6 + m) * HW] = s;
        }
    }
}

// ---------------------------------------------------------------------------
extern "C" void kernel_launch(void* const* d_in, const int* in_sizes, int n_in,
                              void* d_out, int out_size) {
    const float* x    = (const float*)d_in[0];
    const float* w0   = (const float*)d_in[1];
    const float* b0   = (const float*)d_in[2];
    const float* g0   = (const float*)d_in[3];
    const float* be0  = (const float*)d_in[4];
    const float* m0   = (const float*)d_in[5];
    const float* v0   = (const float*)d_in[6];
    const float* wm   = (const float*)d_in[7];
    const float* bm   = (const float*)d_in[8];
    const float* gm   = (const float*)d_in[9];
    const float* bem  = (const float*)d_in[10];
    const float* mm   = (const float*)d_in[11];
    const float* vm   = (const float*)d_in[12];
    const float* wl   = (const float*)d_in[13];
    const float* bl   = (const float*)d_in[14];
    const float* gl   = (const float*)d_in[15];
    const float* bel  = (const float*)d_in[16];
    const float* ml   = (const float*)d_in[17];
    const float* vl   = (const float*)d_in[18];
    const float* bases= (const float*)d_in[19];

    __nv_bfloat16 *p0h, *p0l, *p1h, *p1l;
    float *bco, *shiftT;
    uint32_t* wF;
    cudaGetSymbolAddress((void**)&p0h, g_p0h);
    cudaGetSymbolAddress((void**)&p0l, g_p0l);
    cudaGetSymbolAddress((void**)&p1h, g_p1h);
    cudaGetSymbolAddress((void**)&p1l, g_p1l);
    cudaGetSymbolAddress((void**)&bco,  g_bcoef);
    cudaGetSymbolAddress((void**)&wF,   g_wF);
    cudaGetSymbolAddress((void**)&shiftT, g_shiftT);

    cudaFuncSetAttribute(conv_mma_t<0>, cudaFuncAttributeMaxDynamicSharedMemorySize, SMEM_BYTES);
    cudaFuncSetAttribute(conv_mma_t<1>, cudaFuncAttributeMaxDynamicSharedMemorySize, SMEM_BYTES);

    dim3 pgrd(9, 7);
    prep_weights<<<pgrd, 256>>>(w0, b0, g0, be0, m0, v0,
                                wm, bm, gm, bem, mm, vm,
                                wl, bl, gl, bel, ml, vl, wF, shiftT);

    dim3 sgrd(128, NBATCH);
    split_input<<<sgrd, 128>>>(x, p0h, p0l);

    __nv_bfloat16* hbuf[2] = { p0h, p1h };
    __nv_bfloat16* lbuf[2] = { p0l, p1l };
    for (int l = 0; l < 6; l++) {
        conv_mma_t<0><<<sgrd, 256, SMEM_BYTES>>>(
            hbuf[l & 1], lbuf[l & 1], hbuf[(l + 1) & 1], lbuf[(l + 1) & 1],
            wF + (size_t)l * 36864, shiftT + l * 64, nullptr, nullptr);
    }
    // last layer (64->36) + bcoef, reads layer-5 output planes (p0h/p0l)
    conv_mma_t<1><<<sgrd, 256, SMEM_BYTES>>>(
        p0h, p0l, nullptr, nullptr,
        wF + (size_t)6 * 36864, shiftT + 6 * 64, bases, bco);

    dim3 grd2(HW / 256, NBATCH);
    dynconv<<<grd2, 256>>>(x, bco, (float*)d_out);
}

// round 11
// speedup vs baseline: 3.7726x; 2.0962x over previous
#include <cuda_runtime.h>
#include <cuda_bf16.h>
#include <cuda_fp16.h>
#include <cstdint>

#define HH 128
#define WWID 128
#define NBATCH 8
#define CIN 64
#define HW (HH*WWID)

// ---------------- device scratch ----------------
__device__ __half g_q0[NBATCH * HW * CIN];     // channel-last fp16 plane
__device__ __half g_q1[NBATCH * HW * CIN];
__device__ float g_bcoef[NBATCH * 54 * HW];
__device__ uint32_t g_wF[7 * 9 * 2048];        // [l][tap][kc][nh][lane][8] fragment regs
__device__ float g_shiftT[7 * 64];

// smem layout (bytes): A halo 3 slots (dy) of 130px*144B = 18720B -> 56160
// shift @56160 (256B), bases @56416 (216B).
// acc (128*66*4 = 33792) and hs (@34816, 128*40*4) reuse the A region.
#define A_SLOT 18720u
#define SH_OFF 56160u
#define BAS_OFF 56416u
#define HS_OFF 34816u
#define SMEM_BYTES 56704

__device__ __forceinline__ float tanh_fast(float x) {
    float a = fminf(fmaxf(x, -9.f), 9.f);
    float e = __expf(2.f * a);
    return __fdividef(e - 1.f, e + 1.f);
}
__device__ __forceinline__ void cp16(uint32_t dst, const void* src) {
    asm volatile("cp.async.cg.shared.global [%0], [%1], 16;" :: "r"(dst), "l"(src));
}
__device__ __forceinline__ uint32_t s2u(const void* p) {
    return (uint32_t)__cvta_generic_to_shared(p);
}
__device__ __forceinline__ void ldsm4(uint32_t* a, uint32_t addr) {
    asm volatile("ldmatrix.sync.aligned.m8n8.x4.shared.b16 {%0,%1,%2,%3}, [%4];"
                 : "=r"(a[0]), "=r"(a[1]), "=r"(a[2]), "=r"(a[3]) : "r"(addr));
}
__device__ __forceinline__ void mma16816(float* c, const uint32_t* a, const uint32_t* b) {
    asm volatile("mma.sync.aligned.m16n8k16.row.col.f32.f16.f16.f32 "
                 "{%0,%1,%2,%3}, {%4,%5,%6,%7}, {%8,%9}, {%0,%1,%2,%3};"
                 : "+f"(c[0]), "+f"(c[1]), "+f"(c[2]), "+f"(c[3])
                 : "r"(a[0]), "r"(a[1]), "r"(a[2]), "r"(a[3]), "r"(b[0]), "r"(b[1]));
}

// ---------------------------------------------------------------------------
// Prep: BN-fold weights -> fp16 per-lane MMA fragments.
// reg r = nt*2 + j:  n = nh*32 + nt*8 + lane/4,  k = kc*16 + (lane%4)*2 + j*8
// Layers 0..5: 64 oc. Layer 6 (last): 36 oc zero-padded to 64.
// ---------------------------------------------------------------------------
__global__ void prep_weights(
    const float* __restrict__ w0, const float* __restrict__ b0,
    const float* __restrict__ g0, const float* __restrict__ be0,
    const float* __restrict__ m0, const float* __restrict__ v0,
    const float* __restrict__ wm, const float* __restrict__ bm,
    const float* __restrict__ gm, const float* __restrict__ bem,
    const float* __restrict__ mm, const float* __restrict__ vm,
    const float* __restrict__ wl, const float* __restrict__ bl,
    const float* __restrict__ gl, const float* __restrict__ bel,
    const float* __restrict__ ml, const float* __restrict__ vl,
    uint32_t* __restrict__ wF, float* __restrict__ shiftT)
{
    const int tap = blockIdx.x, l = blockIdx.y;
    const float *w, *bb, *g, *be, *m, *v;
    int OC = 64;
    if (l == 0)      { w = w0; bb = b0; g = g0; be = be0; m = m0; v = v0; }
    else if (l <= 5) {
        int i = l - 1;
        w = wm + (size_t)i * 64 * 64 * 9; bb = bm + i * 64; g = gm + i * 64;
        be = bem + i * 64; m = mm + i * 64; v = vm + i * 64;
    } else { w = wl; bb = bl; g = gl; be = bel; m = ml; v = vl; OC = 36; }

    uint32_t* out = wF + (size_t)(l * 9 + tap) * 2048;
    for (int e = threadIdx.x; e < 2048; e += blockDim.x) {
        int kc = e >> 9, nh = (e >> 8) & 1, lane = (e >> 3) & 31, r = e & 7;
        int nt = r >> 1, j = r & 1;
        int n = nh * 32 + nt * 8 + (lane >> 2);
        int k = kc * 16 + (lane & 3) * 2 + j * 8;
        float f0 = 0.f, f1 = 0.f;
        if (n < OC) {
            float sc = g[n] * rsqrtf(v[n] + 1e-5f);
            f0 = w[((size_t)n * 64 + k) * 9 + tap] * sc;
            f1 = w[((size_t)n * 64 + k + 1) * 9 + tap] * sc;
        }
        unsigned u0 = __half_as_ushort(__float2half_rn(f0));
        unsigned u1 = __half_as_ushort(__float2half_rn(f1));
        out[e] = u0 | (u1 << 16);
    }
    if (tap == 0)
        for (int oc = threadIdx.x; oc < 64; oc += blockDim.x) {
            float s = 0.f;
            if (oc < OC) {
                float sc = g[oc] * rsqrtf(v[oc] + 1e-5f);
                s = (bb[oc] - m[oc]) * sc + be[oc];
            }
            shiftT[l * 64 + oc] = s;
        }
}

// ---------------------------------------------------------------------------
// x [b][c][h][w] fp32 -> channel-last fp16 [b][h][w][c]
// ---------------------------------------------------------------------------
__global__ __launch_bounds__(128) void conv_input(
    const float* __restrict__ x, __half* __restrict__ XQ)
{
    const int w = threadIdx.x, r = blockIdx.x, b = blockIdx.y;
    unsigned hp[32];
    #pragma unroll
    for (int j = 0; j < 32; j++) {
        float f0 = x[((size_t)(b * 64 + 2 * j) * 128 + r) * 128 + w];
        float f1 = x[((size_t)(b * 64 + 2 * j + 1) * 128 + r) * 128 + w];
        hp[j] = (unsigned)__half_as_ushort(__float2half_rn(f0)) |
                ((unsigned)__half_as_ushort(__float2half_rn(f1)) << 16);
    }
    uint4* dh = (uint4*)(XQ + ((size_t)(b * 128 + r) * 128 + w) * 64);
    #pragma unroll
    for (int q = 0; q < 8; q++)
        dh[q] = make_uint4(hp[4*q], hp[4*q+1], hp[4*q+2], hp[4*q+3]);
}

// ---------------------------------------------------------------------------
// Warp-MMA conv layer, fp16 single product, B fragments via LDG.
// CTA = (row, batch). 8 warps = 4 M-stripes(32px) x 2 N-halves(32oc).
// LAST=0: BN+tanh -> fp16 plane.  LAST=1 (64->36): + bcoef einsum.
// ---------------------------------------------------------------------------
template<int LAST>
__global__ __launch_bounds__(256) void conv_mma_t(
    const __half* __restrict__ XQ, __half* __restrict__ YQ,
    const uint32_t* __restrict__ wFl, const float* __restrict__ shiftl,
    const float* __restrict__ bases, float* __restrict__ bco)
{
    extern __shared__ __align__(16) char sm[];
    const uint32_t alu = s2u(sm);
    const int tid = threadIdx.x, lane = tid & 31, wid = tid >> 5;
    const int ms = wid >> 1, nh = wid & 1;
    const int r = blockIdx.x, b = blockIdx.y;

    const uint32_t aoff = (uint32_t)(lane & 15) * 144u + (uint32_t)((lane >> 4) & 1) * 16u;

    if (tid < 64) ((float*)(sm + SH_OFF))[tid] = shiftl[tid];
    if (LAST && tid < 54) ((float*)(sm + BAS_OFF))[tid] = bases[tid];

    // zero halo edge pixels (px 0, 129) of 3 A slots; off-image rows
    {
        uint4 z = make_uint4(0, 0, 0, 0);
        for (int i = tid; i < 48; i += 256) {
            int slot = i >> 4, jj = (i >> 3) & 1, c = i & 7;
            *(uint4*)(sm + slot * A_SLOT + (jj ? 129 : 0) * 144 + c * 16) = z;
        }
        if (r == 0 || r == 127) {
            char* base = sm + (r ? 2 : 0) * A_SLOT;
            for (int i = tid; i < 1170; i += 256)
                *(uint4*)(base + i * 16) = z;
        }
    }

    // ---- async copies: A halo rows ----
    #pragma unroll
    for (int dy = 0; dy < 3; dy++) {
        int rimg = r + dy - 1;
        if ((unsigned)rimg >= (unsigned)HH) continue;
        const char* src = (const char*)XQ + (size_t)(b * 128 + rimg) * 16384;
        uint32_t dstb = alu + (uint32_t)dy * A_SLOT;
        for (int i = tid; i < 1024; i += 256) {
            int px = i >> 3, c = i & 7;
            cp16(dstb + (uint32_t)(px + 1) * 144u + (uint32_t)c * 16u,
                 src + px * 128 + c * 16);
        }
    }
    asm volatile("cp.async.commit_group;" ::: "memory");
    asm volatile("cp.async.wait_group 0;" ::: "memory");
    __syncthreads();

    float cacc[2][4][4];
    #pragma unroll
    for (int mt = 0; mt < 2; mt++)
        #pragma unroll
        for (int nt = 0; nt < 4; nt++)
            #pragma unroll
            for (int j = 0; j < 4; j++) cacc[mt][nt][j] = 0.f;

    // ---- mainloop: 9 taps, fp16 single product ----
    #pragma unroll 1
    for (int tap = 0; tap < 9; tap++) {
        const int dy = tap / 3, dx = tap % 3;
        const uint32_t aB = alu + (uint32_t)dy * A_SLOT + (uint32_t)dx * 144u;
        #pragma unroll
        for (int kc = 0; kc < 4; kc++) {
            const uint4* f = (const uint4*)(wFl +
                ((((size_t)tap * 4 + kc) * 2 + nh) * 32 + lane) * 8);
            uint4 q0 = f[0], q1 = f[1];

            const uint32_t kb = (uint32_t)kc * 32u;
            uint32_t ah[2][4];
            ldsm4(ah[0], aB + (uint32_t)(ms * 32) * 144u + kb + aoff);
            ldsm4(ah[1], aB + (uint32_t)(ms * 32 + 16) * 144u + kb + aoff);

            uint32_t bh[4][2];
            bh[0][0] = q0.x; bh[0][1] = q0.y; bh[1][0] = q0.z; bh[1][1] = q0.w;
            bh[2][0] = q1.x; bh[2][1] = q1.y; bh[3][0] = q1.z; bh[3][1] = q1.w;

            #pragma unroll
            for (int mt = 0; mt < 2; mt++)
                #pragma unroll
                for (int nt = 0; nt < 4; nt++)
                    mma16816(cacc[mt][nt], ah[mt], bh[nt]);
        }
    }
    __syncthreads();   // A region now reusable as acc

    // ---- accumulators -> smem [128 px][66-stride fp32] ----
    float* acc = (float*)sm;
    {
        const int rb = ms * 32 + (lane >> 2);
        const int cb = nh * 32 + (lane & 3) * 2;
        #pragma unroll
        for (int mt = 0; mt < 2; mt++)
            #pragma unroll
            for (int nt = 0; nt < 4; nt++) {
                int row = rb + mt * 16, col = cb + nt * 8;
                *(float2*)&acc[row * 66 + col] =
                    make_float2(cacc[mt][nt][0], cacc[mt][nt][1]);
                *(float2*)&acc[(row + 8) * 66 + col] =
                    make_float2(cacc[mt][nt][2], cacc[mt][nt][3]);
            }
    }
    __syncthreads();

    if (!LAST) {
        // ---- epilogue: tanh -> fp16 plane ----
        const int px = tid >> 1, ocb = (tid & 1) * 32;
        const float* shp = (const float*)(sm + SH_OFF) + ocb;
        const float* ap = acc + px * 66 + ocb;
        unsigned hp[16];
        #pragma unroll
        for (int j = 0; j < 16; j++) {
            float t0 = tanh_fast(ap[2 * j] + shp[2 * j]);
            float t1 = tanh_fast(ap[2 * j + 1] + shp[2 * j + 1]);
            hp[j] = (unsigned)__half_as_ushort(__float2half_rn(t0)) |
                    ((unsigned)__half_as_ushort(__float2half_rn(t1)) << 16);
        }
        uint4* dh = (uint4*)(YQ + ((size_t)(b * 128 + r) * 128 + px) * 64 + ocb);
        #pragma unroll
        for (int q = 0; q < 4; q++)
            dh[q] = make_uint4(hp[4*q], hp[4*q+1], hp[4*q+2], hp[4*q+3]);
    } else {
        // ---- epilogue: tanh (36 oc) -> hs, then bcoef einsum ----
        float* hsP = (float*)(sm + HS_OFF);
        const float* shp = (const float*)(sm + SH_OFF);
        {
            const int px = tid >> 1, half = tid & 1;
            #pragma unroll
            for (int j = 0; j < 18; j++) {
                int oc = half * 18 + j;
                hsP[px * 40 + oc] = tanh_fast(acc[px * 66 + oc] + shp[oc]);
            }
        }
        __syncthreads();
        {
            const int px = tid >> 1, half = tid & 1;
            const float* basS = (const float*)(sm + BAS_OFF);
            const float* hp = hsP + px * 40;
            #pragma unroll
            for (int mm = 0; mm < 3; mm++) {
                int m = half * 3 + mm;
                float hm[6];
                #pragma unroll
                for (int k = 0; k < 6; k++) hm[k] = hp[m * 6 + k];
                #pragma unroll
                for (int l = 0; l < 9; l++) {
                    float s = 0.f;
                    #pragma unroll
                    for (int k = 0; k < 6; k++) s = fmaf(hm[k], basS[k * 9 + l], s);
                    bco[((size_t)(b * 6 + m) * 9 + l) * HW + r * 128 + px] = s;
                }
            }
        }
    }
}

// ---------------------------------------------------------------------------
__global__ __launch_bounds__(256) void dynconv(
    const float* __restrict__ x, const float* __restrict__ bco,
    float* __restrict__ out)
{
    const int b = blockIdx.y;
    const int pix = blockIdx.x * 256 + threadIdx.x;
    const int h = pix >> 7, w = pix & 127;

    float bc[54];
    const float* bcb = bco + (size_t)b * 54 * HW + pix;
    #pragma unroll
    for (int i = 0; i < 54; i++) bc[i] = bcb[(size_t)i * HW];

    bool ok[9]; int off[9];
    #pragma unroll
    for (int dy = 0; dy < 3; dy++)
        #pragma unroll
        for (int dx = 0; dx < 3; dx++) {
            int k = dy * 3 + dx;
            int hh = h + dy - 1, ww = w + dx - 1;
            ok[k] = ((unsigned)hh < HH) && ((unsigned)ww < WWID);
            off[k] = hh * WWID + ww;
        }

    const float* xb = x + (size_t)b * CIN * HW;
    float* ob = out + (size_t)b * (CIN * 6) * HW + pix;

    for (int c = 0; c < CIN; c++) {
        const float* xc = xb + c * HW;
        float v[9];
        #pragma unroll
        for (int k = 0; k < 9; k++) v[k] = ok[k] ? __ldg(xc + off[k]) : 0.f;
        #pragma unroll
        for (int m = 0; m < 6; m++) {
            float s = 0.f;
            #pragma unroll
            for (int k = 0; k < 9; k++) s = fmaf(bc[m * 9 + k], v[k], s);
            ob[(size_t)(c * 6 + m) * HW] = s;
        }
    }
}

// ---------------------------------------------------------------------------
extern "C" void kernel_launch(void* const* d_in, const int* in_sizes, int n_in,
                              void* d_out, int out_size) {
    const float* x    = (const float*)d_in[0];
    const float* w0   = (const float*)d_in[1];
    const float* b0   = (const float*)d_in[2];
    const float* g0   = (const float*)d_in[3];
    const float* be0  = (const float*)d_in[4];
    const float* m0   = (const float*)d_in[5];
    const float* v0   = (const float*)d_in[6];
    const float* wm   = (const float*)d_in[7];
    const float* bm   = (const float*)d_in[8];
    const float* gm   = (const float*)d_in[9];
    const float* bem  = (const float*)d_in[10];
    const float* mm   = (const float*)d_in[11];
    const float* vm   = (const float*)d_in[12];
    const float* wl   = (const float*)d_in[13];
    const float* bl   = (const float*)d_in[14];
    const float* gl   = (const float*)d_in[15];
    const float* bel  = (const float*)d_in[16];
    const float* ml   = (const float*)d_in[17];
    const float* vl   = (const float*)d_in[18];
    const float* bases= (const float*)d_in[19];

    __half *q0, *q1;
    float *bco, *shiftT;
    uint32_t* wF;
    cudaGetSymbolAddress((void**)&q0, g_q0);
    cudaGetSymbolAddress((void**)&q1, g_q1);
    cudaGetSymbolAddress((void**)&bco,  g_bcoef);
    cudaGetSymbolAddress((void**)&wF,   g_wF);
    cudaGetSymbolAddress((void**)&shiftT, g_shiftT);

    cudaFuncSetAttribute(conv_mma_t<0>, cudaFuncAttributeMaxDynamicSharedMemorySize, SMEM_BYTES);
    cudaFuncSetAttribute(conv_mma_t<1>, cudaFuncAttributeMaxDynamicSharedMemorySize, SMEM_BYTES);

    dim3 pgrd(9, 7);
    prep_weights<<<pgrd, 256>>>(w0, b0, g0, be0, m0, v0,
                                wm, bm, gm, bem, mm, vm,
                                wl, bl, gl, bel, ml, vl, wF, shiftT);

    dim3 sgrd(128, NBATCH);
    conv_input<<<sgrd, 128>>>(x, q0);

    __half* buf[2] = { q0, q1 };
    for (int l = 0; l < 6; l++) {
        conv_mma_t<0><<<sgrd, 256, SMEM_BYTES>>>(
            buf[l & 1], buf[(l + 1) & 1],
            wF + (size_t)l * 9 * 2048, shiftT + l * 64, nullptr, nullptr);
    }
    // last layer (64->36) + bcoef, reads layer-5 output plane (q0)
    conv_mma_t<1><<<sgrd, 256, SMEM_BYTES>>>(
        q0, nullptr,
        wF + (size_t)6 * 9 * 2048, shiftT + 6 * 64, bases, bco);

    dim3 grd2(HW / 256, NBATCH);
    dynconv<<<grd2, 256>>>(x, bco, (float*)d_out);
}